// round 13
// baseline (speedup 1.0000x reference)
#include <cuda_runtime.h>
#include <cstdint>

#define S_LEN 2048
#define D_DIM 2048
#define NH 32
#define NB 8
#define HB 256    // NH*NB

// -------- scratch (no allocations allowed) --------
__device__ float g_pq[NH * S_LEN * NB];   // [h][s][bit], pre-scaled by 2
__device__ float g_pk[NH * S_LEN * NB];
__device__ float g_pv[NH * S_LEN * NB];
__device__ float g_sumk[NH * S_LEN];
__device__ float g_op[S_LEN * HB];        // (e1-e0)*attn_out
__device__ float g_bias[D_DIM];           // e0 @ Wo

__device__ __forceinline__ float fsigmoid(float x) {
    return 1.0f / (1.0f + __expf(-x));
}
__device__ __forceinline__ uint32_t smem_u32(const void* p) {
    uint32_t a;
    asm("{ .reg .u64 t; cvta.to.shared.u64 t, %1; cvt.u32.u64 %0, t; }" : "=r"(a) : "l"(p));
    return a;
}
__device__ __forceinline__ void cp16(uint32_t dst, const void* src) {
    asm volatile("cp.async.cg.shared.global [%0], [%1], 16;" :: "r"(dst), "l"(src));
}
__device__ __forceinline__ void cp_commit() {
    asm volatile("cp.async.commit_group;" ::: "memory");
}
template <int N> __device__ __forceinline__ void cp_wait() {
    asm volatile("cp.async.wait_group %0;" :: "n"(N) : "memory");
}
__device__ __forceinline__ void fma2(float2& d, float2 a, float2 b) {
    asm("fma.rn.f32x2 %0, %1, %2, %0;"
        : "+l"(reinterpret_cast<unsigned long long&>(d))
        : "l"(reinterpret_cast<unsigned long long&>(a)),
          "l"(reinterpret_cast<unsigned long long&>(b)));
}
__device__ __forceinline__ float2 dup2(float a) {
    float2 r;
    asm("mov.b64 %0, {%1, %1};"
        : "=l"(reinterpret_cast<unsigned long long&>(r)) : "f"(a));
    return r;
}

// ---------------- f32 GEMM core (PROVEN in R12) ----------------
#define GBK 16
#define AROW 20
#define ASZ (128 * AROW)        // 2560 floats
#define BSZ (GBK * 128)         // 2048 floats
#define GEMM_SMEM_FLOATS (2 * ASZ + 2 * BSZ)   // 9216 floats = 36864 B

__device__ __forceinline__ void g_load_chunk(
    const float* __restrict__ A, const float* __restrict__ B,
    int K, int Nst, int arow0, int bcol, int k0,
    float* as, float* bs, int tid)
{
#pragma unroll
    for (int i = 0; i < 2; ++i) {
        int idx = tid + i * 256;
        int r = idx >> 2, q = idx & 3;
        cp16(smem_u32(as + r * AROW + q * 4),
             A + (size_t)(arow0 + r) * K + k0 + q * 4);
    }
#pragma unroll
    for (int i = 0; i < 2; ++i) {
        int idx = tid + i * 256;
        int kr = idx >> 5, nq = idx & 31;
        cp16(smem_u32(bs + kr * 128 + nq * 4),
             B + (size_t)(k0 + kr) * Nst + bcol + nq * 4);
    }
}

__device__ __forceinline__ void g_compute_chunk(
    const float* __restrict__ as, const float* __restrict__ bs,
    int m0, int n0, float2 (&acc)[8][4])
{
#pragma unroll
    for (int k = 0; k < GBK; ++k) {
        float a[8];
#pragma unroll
        for (int mi = 0; mi < 8; ++mi) a[mi] = as[(m0 + mi) * AROW + k];
        float4 b0 = *(const float4*)&bs[k * 128 + n0];
        float4 b1 = *(const float4*)&bs[k * 128 + n0 + 4];
        float2 b2[4] = {{b0.x, b0.y}, {b0.z, b0.w}, {b1.x, b1.y}, {b1.z, b1.w}};
#pragma unroll
        for (int mi = 0; mi < 8; ++mi) {
            float2 am = dup2(a[mi]);
#pragma unroll
            for (int n2 = 0; n2 < 4; ++n2) fma2(acc[mi][n2], am, b2[n2]);
        }
    }
}

// ---------------- qkv GEMM (R12 core, qkv part only) ----------------
// grid (6, 16): x>>1 = {Wq,Wk,Wv}, (x&1)*128 = col tile.
__global__ void __launch_bounds__(256) qkv_gemm(
    const float* __restrict__ hs, const float* __restrict__ Wq,
    const float* __restrict__ Wk, const float* __restrict__ Wv)
{
    __shared__ __align__(16) float As[2][ASZ];
    __shared__ __align__(16) float Bs[2][BSZ];

    const int tid = threadIdx.x;
    const int mat = blockIdx.x >> 1;
    const float* Bsrc = (mat == 0) ? Wq : (mat == 1) ? Wk : Wv;
    const int bcol = (blockIdx.x & 1) * 128;
    const int brow = blockIdx.y * 128;

    float2 acc[8][4];
#pragma unroll
    for (int mi = 0; mi < 8; ++mi)
#pragma unroll
        for (int n2 = 0; n2 < 4; ++n2) acc[mi][n2] = make_float2(0.f, 0.f);

    const int m0 = (tid >> 4) * 8, n0 = (tid & 15) * 8;
    const int nch = D_DIM / GBK;

    g_load_chunk(hs, Bsrc, D_DIM, HB, brow, bcol, 0, As[0], Bs[0], tid);
    cp_commit();
    for (int c = 0; c < nch; ++c) {
        if (c + 1 < nch)
            g_load_chunk(hs, Bsrc, D_DIM, HB, brow, bcol, (c + 1) * GBK,
                         As[(c + 1) & 1], Bs[(c + 1) & 1], tid);
        cp_commit();
        cp_wait<1>();
        __syncthreads();
        g_compute_chunk(As[c & 1], Bs[c & 1], m0, n0, acc);
        __syncthreads();
    }

    float* dst = (mat == 0) ? g_pq : (mat == 1) ? g_pk : g_pv;
    const float scl = (mat == 0) ? 2.0f : 1.0f;
#pragma unroll
    for (int mi = 0; mi < 8; ++mi) {
        int s = brow + m0 + mi;
#pragma unroll
        for (int n2 = 0; n2 < 4; ++n2) {
            int c = bcol + n0 + 2 * n2;
            int h = c >> 3, d = c & 7;
            float2 v = acc[mi][n2];
            v.x = scl * fsigmoid(v.x);
            v.y = scl * fsigmoid(v.y);
            *(float2*)&dst[((size_t)h * S_LEN + s) * NB + d] = v;
        }
    }
}

// ---------------- combined: gate GEMM tiles || attention tiles ----------------
// grid 512 x 256thr. even bid -> gate tile (16x16 tiles of 128x128);
// odd bid -> attention tile (256 q-rows; 32 heads x 8 q-tiles).
__global__ void __launch_bounds__(256, 2) combined_kernel(
    const float* __restrict__ hs, const float* __restrict__ Wg,
    const float* __restrict__ e0, const float* __restrict__ e1,
    float* __restrict__ out)
{
    extern __shared__ __align__(16) float smem[];
    const int tid = threadIdx.x;
    const int bid = blockIdx.x;

    if ((bid & 1) == 0) {
        // ---- gate GEMM tile (R12 core) ----
        float* As0 = smem;
        float* As1 = smem + ASZ;
        float* Bs0 = smem + 2 * ASZ;
        float* Bs1 = smem + 2 * ASZ + BSZ;
        const int gidx = bid >> 1;
        const int bcol = (gidx & 15) * 128;
        const int brow = (gidx >> 4) * 128;

        float2 acc[8][4];
#pragma unroll
        for (int mi = 0; mi < 8; ++mi)
#pragma unroll
            for (int n2 = 0; n2 < 4; ++n2) acc[mi][n2] = make_float2(0.f, 0.f);

        const int m0 = (tid >> 4) * 8, n0 = (tid & 15) * 8;
        const int nch = D_DIM / GBK;

        g_load_chunk(hs, Wg, D_DIM, D_DIM, brow, bcol, 0, As0, Bs0, tid);
        cp_commit();
        for (int c = 0; c < nch; ++c) {
            if (c + 1 < nch)
                g_load_chunk(hs, Wg, D_DIM, D_DIM, brow, bcol, (c + 1) * GBK,
                             ((c + 1) & 1) ? As1 : As0, ((c + 1) & 1) ? Bs1 : Bs0, tid);
            cp_commit();
            cp_wait<1>();
            __syncthreads();
            g_compute_chunk((c & 1) ? As1 : As0, (c & 1) ? Bs1 : Bs0, m0, n0, acc);
            __syncthreads();
        }

#pragma unroll
        for (int mi = 0; mi < 8; ++mi) {
            int r = brow + m0 + mi;
            size_t base = (size_t)r * D_DIM + bcol + n0;
            *(float4*)&out[base] =
                make_float4(acc[mi][0].x, acc[mi][0].y, acc[mi][1].x, acc[mi][1].y);
            *(float4*)&out[base + 4] =
                make_float4(acc[mi][2].x, acc[mi][2].y, acc[mi][3].x, acc[mi][3].y);
        }
    } else {
        // ---- attention tile: 256 q-rows, one head ----
        float* sk = smem;                 // 256*8 floats
        float* sv = smem + 2048;          // 256*8 floats
        float* ssum = smem + 4096;        // 256 floats
        const int aidx = bid >> 1;
        const int h = aidx >> 3;
        const int qt = aidx & 7;
        const int q = qt * 256 + tid;

        float pq[8];
        {
            const float4* p = (const float4*)&g_pq[((size_t)h * S_LEN + q) * NB];
            float4 p0 = p[0], p1 = p[1];
            pq[0] = p0.x; pq[1] = p0.y; pq[2] = p0.z; pq[3] = p0.w;
            pq[4] = p1.x; pq[5] = p1.y; pq[6] = p1.z; pq[7] = p1.w;
        }
        float acc[8] = {0, 0, 0, 0, 0, 0, 0, 0};
        float l = 0.f;

        const float* kbase = &g_pk[(size_t)h * S_LEN * NB];
        const float* vbase = &g_pv[(size_t)h * S_LEN * NB];

        for (int kt = 0; kt <= qt; ++kt) {
            const float4* kp = (const float4*)(kbase + (size_t)kt * 256 * NB);
            const float4* vp = (const float4*)(vbase + (size_t)kt * 256 * NB);
            ((float4*)sk)[tid]       = kp[tid];
            ((float4*)sk)[tid + 256] = kp[tid + 256];
            ((float4*)sv)[tid]       = vp[tid];
            ((float4*)sv)[tid + 256] = vp[tid + 256];
            ssum[tid] = g_sumk[h * S_LEN + kt * 256 + tid];
            __syncthreads();

            const int kmax = (kt == qt) ? (tid + 1) : 256;
            const float4* sk4 = (const float4*)sk;
            const float4* sv4 = (const float4*)sv;
            for (int kk = 0; kk < kmax; ++kk) {
                float4 k0 = sk4[kk * 2];
                float4 k1 = sk4[kk * 2 + 1];
                float dot = -ssum[kk];
                dot = fmaf(pq[0], k0.x, dot); dot = fmaf(pq[1], k0.y, dot);
                dot = fmaf(pq[2], k0.z, dot); dot = fmaf(pq[3], k0.w, dot);
                dot = fmaf(pq[4], k1.x, dot); dot = fmaf(pq[5], k1.y, dot);
                dot = fmaf(pq[6], k1.z, dot); dot = fmaf(pq[7], k1.w, dot);
                float e = __expf(dot);
                l += e;
                float4 v0 = sv4[kk * 2];
                float4 v1 = sv4[kk * 2 + 1];
                acc[0] = fmaf(e, v0.x, acc[0]); acc[1] = fmaf(e, v0.y, acc[1]);
                acc[2] = fmaf(e, v0.z, acc[2]); acc[3] = fmaf(e, v0.w, acc[3]);
                acc[4] = fmaf(e, v1.x, acc[4]); acc[5] = fmaf(e, v1.y, acc[5]);
                acc[6] = fmaf(e, v1.z, acc[6]); acc[7] = fmaf(e, v1.w, acc[7]);
            }
            __syncthreads();
        }

        float inv = 1.0f / l;
        float o[8];
#pragma unroll
        for (int d = 0; d < 8; ++d) {
            int j = h * 8 + d;
            o[d] = acc[d] * inv * (e1[j] - e0[j]);
        }
        float4* outp = (float4*)&g_op[(size_t)q * HB + h * 8];
        outp[0] = make_float4(o[0], o[1], o[2], o[3]);
        outp[1] = make_float4(o[4], o[5], o[6], o[7]);
    }
}

// ---------------- final GEMM (R12, PROVEN) ----------------
__global__ void __launch_bounds__(256) final_gemm(
    const float* __restrict__ Wo, float* __restrict__ out)
{
    __shared__ __align__(16) float As[2][ASZ];
    __shared__ __align__(16) float Bs[2][BSZ];

    const int tid = threadIdx.x;
    const int brow = blockIdx.y * 128;
    const int bcol = blockIdx.x * 128;

    float2 acc[8][4];
#pragma unroll
    for (int mi = 0; mi < 8; ++mi)
#pragma unroll
        for (int n2 = 0; n2 < 4; ++n2) acc[mi][n2] = make_float2(0.f, 0.f);

    const int m0 = (tid >> 4) * 8, n0 = (tid & 15) * 8;
    const int nch = HB / GBK;

    g_load_chunk(g_op, Wo, HB, D_DIM, brow, bcol, 0, As[0], Bs[0], tid);
    cp_commit();
    for (int c = 0; c < nch; ++c) {
        if (c + 1 < nch)
            g_load_chunk(g_op, Wo, HB, D_DIM, brow, bcol, (c + 1) * GBK,
                         As[(c + 1) & 1], Bs[(c + 1) & 1], tid);
        cp_commit();
        cp_wait<1>();
        __syncthreads();
        g_compute_chunk(As[c & 1], Bs[c & 1], m0, n0, acc);
        __syncthreads();
    }

#pragma unroll
    for (int mi = 0; mi < 8; ++mi) {
        int r = brow + m0 + mi;
        int c0 = bcol + n0;
        size_t base = (size_t)r * D_DIM + c0;
#pragma unroll
        for (int n2 = 0; n2 < 4; ++n2) {
            float2 b = *(float2*)&g_bias[c0 + 2 * n2];
            float2 g = *(float2*)&out[base + 2 * n2];
            float2 v;
            v.x = (acc[mi][n2].x + b.x) * fsigmoid(g.x);
            v.y = (acc[mi][n2].y + b.y) * fsigmoid(g.y);
            *(float2*)&out[base + 2 * n2] = v;
        }
    }
}

// ---------------- small kernels (PROVEN) ----------------
__global__ void sumk_kernel() {
    int idx = blockIdx.x * blockDim.x + threadIdx.x;
    if (idx < NH * S_LEN) {
        const float* p = &g_pk[(size_t)idx * NB];
        float s = 0.f;
#pragma unroll
        for (int d = 0; d < NB; ++d) s += p[d];
        g_sumk[idx] = s;
    }
}

__global__ void bias_kernel(const float* __restrict__ e0, const float* __restrict__ Wo) {
    int n = blockIdx.x * blockDim.x + threadIdx.x;
    if (n < D_DIM) {
        float s = 0.f;
        for (int j = 0; j < HB; ++j) s = fmaf(e0[j], Wo[(size_t)j * D_DIM + n], s);
        g_bias[n] = s;
    }
}

// ---------------- launch ----------------
extern "C" void kernel_launch(void* const* d_in, const int* in_sizes, int n_in,
                              void* d_out, int out_size)
{
    (void)in_sizes; (void)n_in; (void)out_size;
    const float* hs = (const float*)d_in[0];
    const float* Wq = (const float*)d_in[1];
    const float* Wk = (const float*)d_in[2];
    const float* Wv = (const float*)d_in[3];
    const float* Wo = (const float*)d_in[4];
    const float* Wg = (const float*)d_in[5];
    const float* e0 = (const float*)d_in[6];
    const float* e1 = (const float*)d_in[7];
    float* out = (float*)d_out;

    bias_kernel<<<(D_DIM + 255) / 256, 256>>>(e0, Wo);

    // qkv projections (needed by attention)
    qkv_gemm<<<dim3(6, S_LEN / 128), 256>>>(hs, Wq, Wk, Wv);
    sumk_kernel<<<(NH * S_LEN + 255) / 256, 256>>>();

    // gate GEMM tiles and attention tiles co-scheduled in one launch:
    // gate saturates the FMA pipe, attention rides the idle issue slots.
    combined_kernel<<<512, 256, GEMM_SMEM_FLOATS * sizeof(float)>>>(
        hs, Wg, e0, e1, out);

    // final: out = (g_op @ Wo + bias) * sigmoid(out)
    final_gemm<<<dim3(D_DIM / 128, S_LEN / 128), 256>>>(Wo, out);
}